// round 3
// baseline (speedup 1.0000x reference)
#include <cuda_runtime.h>

#define NTOK 32768
#define DDIM 2048
#define NGRP 16
#define GSZ  4
#define NEXP 64
#define NROW 20
#define DM_OFF (NTOK * 2)
#define LOSS_OFF (NTOK * 2 + NTOK * NEXP)

#define TPB   256                 // 8 warps: 2 per SMSP (one from each k-group)
#define TOKPB 256                 // tokens per block
#define NBLK  (NTOK / TOKPB)      // 128 blocks -> one clean wave
#define KT    32                  // k-tile per group per iteration
#define KHALF (DDIM / 2)          // 1024 k per group
#define NIT   (KHALF / KT)        // 32 iterations
#define XSTR  36                  // 36 mod 32 == 4 -> conflict-free LDS.128
#define XBUF  (TOKPB * XSTR)      // 9216 floats per x buffer
#define WBUF  (NROW * KT)         // 640 floats per w buffer

// floats: 4 x-bufs + 4 w-bufs + part(256*20) aliased into xs0 region? keep separate:
#define PARTF (TOKPB * NROW)
#define SMEM_FLOATS (4 * XBUF + 4 * WBUF + TOKPB * 2 + TOKPB * 2 + NEXP + 2)
#define SMEM_BYTES  (SMEM_FLOATS * 4)

__device__ float g_load[NEXP];
__device__ float g_z[2];

typedef unsigned long long u64;
union F2 { u64 u; float2 f; };

static __device__ __forceinline__ void fma2(u64 &d, u64 a, u64 b) {
    asm("fma.rn.f32x2 %0, %1, %2, %0;" : "+l"(d) : "l"(a), "l"(b));
}
static __device__ __forceinline__ unsigned s2u(const void* p) {
    return (unsigned)__cvta_generic_to_shared(p);
}
static __device__ __forceinline__ void cpa16(unsigned s, const void* g) {
    asm volatile("cp.async.cg.shared.global [%0], [%1], 16;" :: "r"(s), "l"(g));
}
static __device__ __forceinline__ void cpcommit() { asm volatile("cp.async.commit_group;"); }
static __device__ __forceinline__ void cpwait0()  { asm volatile("cp.async.wait_group 0;"); }

__global__ void init_scratch() {
    int i = threadIdx.x;
    if (i < NEXP) g_load[i] = 0.f;
    if (i < 2)    g_z[i] = 0.f;
}

extern __shared__ float smem[];

__global__ __launch_bounds__(TPB, 1) void router_main(
    const float* __restrict__ X, const float* __restrict__ Wg,
    const float* __restrict__ We, float* __restrict__ out)
{
    float* xs[2][2]; float* ws[2][2];
    xs[0][0] = smem;
    xs[0][1] = smem + XBUF;
    xs[1][0] = smem + 2 * XBUF;
    xs[1][1] = smem + 3 * XBUF;
    float* wbase = smem + 4 * XBUF;
    ws[0][0] = wbase;
    ws[0][1] = wbase + WBUF;
    ws[1][0] = wbase + 2 * WBUF;
    ws[1][1] = wbase + 3 * WBUF;
    float* resf  = wbase + 4 * WBUF;               // [256][2] fw1,fw2
    int*   resi  = (int*)(resf + TOKPB * 2);        // [256][2] ei1,ei2
    float* s_load = (float*)(resi + TOKPB * 2);     // [64]
    float* s_z    = s_load + NEXP;                  // [2]
    // partial-logit exchange buffer: alias group-1's x buffers (free after mainloop)
    float* part   = xs[1][0];                       // [256][20]

    const int tid  = threadIdx.x;
    const int lane = tid & 31;
    const int warp = tid >> 5;
    const int grp  = tid >> 7;        // k-half this thread computes
    const int wtid = tid & 127;       // index within warpgroup
    const int T0   = blockIdx.x * TOKPB;

    if (tid < NEXP) s_load[tid] = 0.f;
    if (tid < 2)    s_z[tid] = 0.f;

    unsigned sxu[2][2], swu[2][2];
    #pragma unroll
    for (int g = 0; g < 2; g++)
        #pragma unroll
        for (int b = 0; b < 2; b++) { sxu[g][b] = s2u(xs[g][b]); swu[g][b] = s2u(ws[g][b]); }

    // ---- stage iteration t for BOTH k-groups (all 256 threads cooperate) ----
    auto stage = [&](int t, int b) {
        // x: 2 groups * 256 rows * 8 float4 = 4096
        #pragma unroll
        for (int i = 0; i < 16; i++) {
            int f   = tid + TPB * i;
            int g   = f >> 11;
            int rem = f & 2047;
            int row = rem >> 3, c4 = (rem & 7) << 2;
            cpa16(sxu[g][b] + (unsigned)(row * XSTR + c4) * 4u,
                  X + (size_t)(T0 + row) * DDIM + g * KHALF + t * KT + c4);
        }
        // w: 2 groups * 20 rows * 8 float4 = 320
        #pragma unroll
        for (int i = 0; i < 2; i++) {
            int f = tid + TPB * i;
            if (f < 320) {
                int g   = f >= 160;
                int rem = f - g * 160;
                int r   = rem >> 3, c4 = (rem & 7) << 2;
                const float* src = (r < NGRP)
                    ? (Wg + (size_t)r * DDIM + g * KHALF + t * KT + c4)
                    : (We + (size_t)(r - NGRP) * DDIM + g * KHALF + t * KT + c4);
                cpa16(swu[g][b] + (unsigned)(r * KT + c4) * 4u, src);
            }
        }
        cpcommit();
    };

    u64 acc[NROW][2];
    #pragma unroll
    for (int r = 0; r < NROW; r++) { acc[r][0] = 0ull; acc[r][1] = 0ull; }

    stage(0, 0);
    cpwait0();
    __syncthreads();

    for (int t = 0; t < NIT; t++) {
        if (t + 1 < NIT) stage(t + 1, (t + 1) & 1);

        const float* xb = xs[grp][t & 1];
        const float* wb = ws[grp][t & 1];
        const float* pa = xb + wtid * XSTR;            // token T0 + wtid
        const float* pb = xb + (wtid + 128) * XSTR;    // token T0 + wtid + 128

        #pragma unroll
        for (int kk = 0; kk < KT; kk += 4) {
            ulonglong2 va = *(const ulonglong2*)(pa + kk);
            ulonglong2 vb = *(const ulonglong2*)(pb + kk);
            #pragma unroll
            for (int r = 0; r < NROW; r++) {
                ulonglong2 w = *(const ulonglong2*)(wb + r * KT + kk);  // broadcast
                fma2(acc[r][0], w.x, va.x);
                fma2(acc[r][0], w.y, va.y);
                fma2(acc[r][1], w.x, vb.x);
                fma2(acc[r][1], w.y, vb.y);
            }
        }
        cpwait0();
        __syncthreads();
    }

    // ---- combine split-K partials: group 1 publishes, group 0 finishes ----
    if (grp == 1) {
        #pragma unroll
        for (int s = 0; s < 2; s++) {
            int trow = wtid + s * 128;
            #pragma unroll
            for (int r = 0; r < NROW; r++) {
                F2 u; u.u = acc[r][s];
                part[trow * NROW + r] = u.f.x + u.f.y;
            }
        }
    }
    __syncthreads();

    float zg = 0.f, zl = 0.f;
    if (grp == 0) {
        #pragma unroll
        for (int s = 0; s < 2; s++) {
            const int trow = wtid + s * 128;
            float g[NROW];
            #pragma unroll
            for (int r = 0; r < NROW; r++) {
                F2 u; u.u = acc[r][s];
                g[r] = (u.f.x + u.f.y) + part[trow * NROW + r];
            }

            float sg = 0.f, sl = 0.f;
            #pragma unroll
            for (int i = 0; i < NGRP; i++) sg += g[i] * g[i];
            #pragma unroll
            for (int i = NGRP; i < NROW; i++) sl += g[i] * g[i];
            zg += sg; zl += sl;

            // group softmax + top-1 (first-max tie rule)
            float m = g[0]; int a0 = 0;
            #pragma unroll
            for (int i = 1; i < NGRP; i++) if (g[i] > m) { m = g[i]; a0 = i; }
            float ssum = 0.f;
            #pragma unroll
            for (int i = 0; i < NGRP; i++) ssum += expf(g[i] - m);
            float gw = 1.f / ssum;

            // local softmax over 4 + top-2
            float l0 = g[16], l1 = g[17], l2 = g[18], l3 = g[19];
            float m2 = fmaxf(fmaxf(l0, l1), fmaxf(l2, l3));
            float ev[4] = { expf(l0 - m2), expf(l1 - m2), expf(l2 - m2), expf(l3 - m2) };
            float s2 = ev[0] + ev[1] + ev[2] + ev[3];
            int i1 = 0; float b1 = ev[0];
            #pragma unroll
            for (int j = 1; j < 4; j++) if (ev[j] > b1) { b1 = ev[j]; i1 = j; }
            int i2 = -1; float b2 = -1.f;
            #pragma unroll
            for (int j = 0; j < 4; j++) if (j != i1 && ev[j] > b2) { b2 = ev[j]; i2 = j; }

            float p1v = b1 / s2, p2v = b2 / s2;
            float den = p1v + p2v + 1e-7f;
            float fw1 = gw * (p1v / den);
            float fw2 = gw * (p2v / den);
            int ei1 = (a0 << 2) + i1;
            int ei2 = (a0 << 2) + i2;

            resf[2 * trow] = fw1; resf[2 * trow + 1] = fw2;
            resi[2 * trow] = ei1; resi[2 * trow + 1] = ei2;

            int tok = T0 + trow;
            *(float2*)(out + 2 * tok) = make_float2(fw1, fw2);
            atomicAdd(&s_load[ei1], fw1);
            atomicAdd(&s_load[ei2], fw2);
        }

        #pragma unroll
        for (int m = 16; m >= 1; m >>= 1) {
            zg += __shfl_xor_sync(0xffffffffu, zg, m);
            zl += __shfl_xor_sync(0xffffffffu, zl, m);
        }
        if (lane == 0) { atomicAdd(&s_z[0], zg); atomicAdd(&s_z[1], zl); }
    }
    __syncthreads();

    // dispatch mask: 8 warps, warp w writes rows [32w, 32w+32)
    #pragma unroll 4
    for (int i = 0; i < 32; i++) {
        int trow = (warp << 5) + i;
        int a1 = resi[2 * trow], a2 = resi[2 * trow + 1];
        float f1 = resf[2 * trow], f2 = resf[2 * trow + 1];
        int c = lane << 1;
        float2 v;
        v.x = (c     == a1) ? f1 : ((c     == a2) ? f2 : 0.f);
        v.y = (c + 1 == a1) ? f1 : ((c + 1 == a2) ? f2 : 0.f);
        *(float2*)(out + DM_OFF + (size_t)(T0 + trow) * NEXP + c) = v;
    }

    if (tid < NEXP) atomicAdd(&g_load[tid], s_load[tid]);
    if (tid < 2)    atomicAdd(&g_z[tid], s_z[tid]);
}

__global__ void router_finalize(float* __restrict__ out) {
    int i = threadIdx.x;  // 64 threads
    float v = g_load[i];
    float s = v;
    #pragma unroll
    for (int m = 16; m >= 1; m >>= 1) s += __shfl_xor_sync(0xffffffffu, s, m);
    __shared__ float sh[2];
    if ((i & 31) == 0) sh[i >> 5] = s;
    __syncthreads();
    float total = sh[0] + sh[1];
    float target = total * (1.f / NEXP);
    float dv = v - target;
    float sq = dv * dv;
    #pragma unroll
    for (int m = 16; m >= 1; m >>= 1) sq += __shfl_xor_sync(0xffffffffu, sq, m);
    __shared__ float sh2[2];
    if ((i & 31) == 0) sh2[i >> 5] = sq;
    __syncthreads();
    if (i == 0) {
        float lb = (sh2[0] + sh2[1]) * (1.f / NEXP);
        float z = g_z[0] * (1.f / ((float)NTOK * NGRP)) +
                  g_z[1] * (1.f / ((float)NTOK * GSZ));
        out[LOSS_OFF] = 0.001f * (lb + z);
    }
}

extern "C" void kernel_launch(void* const* d_in, const int* in_sizes, int n_in,
                              void* d_out, int out_size) {
    const float* X  = (const float*)d_in[0];
    const float* Wg = (const float*)d_in[1];
    const float* We = (const float*)d_in[2];
    float* out = (float*)d_out;

    cudaFuncSetAttribute(router_main,
                         cudaFuncAttributeMaxDynamicSharedMemorySize, SMEM_BYTES);

    init_scratch<<<1, 64>>>();
    router_main<<<NBLK, TPB, SMEM_BYTES>>>(X, Wg, We, out);
    router_finalize<<<1, 64>>>(out);
}